// round 14
// baseline (speedup 1.0000x reference)
#include <cuda_runtime.h>
#include <cstddef>

#define Bc 16
#define Fc 4
#define Kc 16
#define KH 8          // k's per block (k-half)
#define Yc 16
#define Xc 16
#define Pc 16
#define Tc 8
#define NT 1024

typedef unsigned long long u64;

// sm_103a packed f32x2 ops (PTX-only; ptxas never auto-fuses these)
__device__ __forceinline__ u64 pk2(float lo, float hi) {
    u64 r; asm("mov.b64 %0, {%1,%2};" : "=l"(r) : "f"(lo), "f"(hi)); return r;
}
__device__ __forceinline__ void unpk2(u64 v, float& lo, float& hi) {
    asm("mov.b64 {%0,%1}, %2;" : "=f"(lo), "=f"(hi) : "l"(v));
}
__device__ __forceinline__ u64 fma2_(u64 a, u64 b, u64 c) {
    u64 d; asm("fma.rn.f32x2 %0, %1, %2, %3;" : "=l"(d) : "l"(a), "l"(b), "l"(c)); return d;
}
__device__ __forceinline__ u64 mul2_(u64 a, u64 b) {
    u64 d; asm("mul.rn.f32x2 %0, %1, %2;" : "=l"(d) : "l"(a), "l"(b)); return d;
}

// One block = (b, f, k-half). 1024 threads: thread = (yh:2b, x:4b, p:4b),
// each thread contracts 4 y-rows (8 t-values each) for 8 k's.
// R8 structure (2 block barriers; integral finalization deferred to the 8
// output threads) with its register flaw fixed: the (klon*klev*dlev) pair
// factor is computed AFTER the main loop (R9/R13-proven), not held across it.
__global__ void __launch_bounds__(NT, 1) pkl_fused(
    const float* __restrict__ field, const float* __restrict__ darea,
    const float* __restrict__ dlev,  const float* __restrict__ dtime,
    const float* __restrict__ lat_mean, const float* __restrict__ lat_logstd,
    const float* __restrict__ lon_mean, const float* __restrict__ lon_logstd,
    const float* __restrict__ lev_mean, const float* __restrict__ lev_logstd,
    const float* __restrict__ time_logtau, float* __restrict__ out)
{
    int blk = blockIdx.x;
    int kh = blk & 1;
    int f  = (blk >> 1) & 3;
    int b  = blk >> 3;
    int tid  = threadIdx.x;
    int lane = tid & 31;
    int warp = tid >> 5;

    __shared__ __align__(16) float sklat[Yc][KH];
    __shared__ __align__(16) float sklon[Xc][KH];
    __shared__ __align__(16) float sklev[Pc][KH];
    __shared__ float srate[KH];
    __shared__ float sdamean[Yc * Xc], sda[Yc * Xc];
    __shared__ float sdlmean[Pc], sdl[Pc], sdtm[Tc], sdt[Tc];
    __shared__ float sred[32][KH];
    __shared__ float sint[8][KH];          // per-warp partial Syx

    // ================= phase 1: params + means =================
    if (tid < 3 * 16 * KH) {
        int j   = tid & 7;
        int d   = (tid >> 3) & 15;
        int dim = tid >> 7;
        int fk  = f * Kc + kh * KH + j;
        float coord = -1.0f + 2.0f * (float)d / 15.0f;
        float m, ls;
        if (dim == 0)      { m = lat_mean[fk]; ls = lat_logstd[fk]; }
        else if (dim == 1) { m = lon_mean[fk]; ls = lon_logstd[fk]; }
        else               { m = lev_mean[fk]; ls = lev_logstd[fk]; }
        float z = (coord - m) * expf(-ls);
        float g = expf(-0.5f * z * z);
        if (dim == 0)      sklat[d][j] = g;
        else if (dim == 1) sklon[d][j] = g;
        else               sklev[d][j] = g;
    }
    if (tid >= 512 && tid < 512 + KH) {
        int j = tid - 512;
        int fk = f * Kc + kh * KH + j;
        float tau = expf(time_logtau[fk]) + 1e-4f;
        srate[j] = expf(-1.0f / tau);       // ktime[t] = rate^t
    }
    if (tid >= 768) {
        int i = tid - 768;
        float s = 0.f;
        #pragma unroll
        for (int bb = 0; bb < Bc; bb++) s += darea[bb * 256 + i];
        sdamean[i] = s * (1.f / 16.f);
        sda[i] = darea[b * 256 + i];
    }
    if (tid >= 704 && tid < 704 + Pc) {
        int i = tid - 704;
        float s = 0.f;
        #pragma unroll
        for (int bb = 0; bb < Bc; bb++) s += dlev[bb * Pc + i];
        sdlmean[i] = s * (1.f / 16.f);
        sdl[i] = dlev[b * Pc + i];
    }
    if (tid >= 736 && tid < 736 + Tc) {
        int i = tid - 736;
        float s = 0.f;
        #pragma unroll
        for (int bb = 0; bb < Bc; bb++) s += dtime[bb * Tc + i];
        sdtm[i] = s * (1.f / 16.f);
        sdt[i] = dtime[b * Tc + i];
    }
    __syncthreads();   // ---- barrier 1 (only block-wide sync before loop) ----

    // ---- integral partials (warps 0-7 only; consumed after barrier 2) ----
    if (warp < 8) {
        int yi = tid >> 4, xi = tid & 15;
        float dm = sdamean[tid];           // tid < 256 here
        #pragma unroll
        for (int j = 0; j < KH; j++) {
            float v = dm * sklat[yi][j] * sklon[xi][j];
            #pragma unroll
            for (int o = 16; o > 0; o >>= 1) v += __shfl_xor_sync(0xFFFFFFFFu, v, o);
            if (lane == 0) sint[warp][j] = v;
        }
    }

    // ================= main contraction (R3/R13 loop) =================
    int p  = tid & 15;
    int x  = (tid >> 4) & 15;
    int yh = tid >> 8;                     // 0..3
    u64 rate2[4];
    #pragma unroll
    for (int jj = 0; jj < 4; jj++)
        rate2[jj] = pk2(srate[2 * jj], srate[2 * jj + 1]);
    float dtr[Tc];
    #pragma unroll
    for (int t = 0; t < Tc; t++) dtr[t] = sdt[t];
    u64 acc[4];
    #pragma unroll
    for (int jj = 0; jj < 4; jj++) acc[jj] = pk2(0.f, 0.f);

    const float4* src = (const float4*)(field
        + (size_t)(b * Fc + f) * (Yc * Xc * Pc * Tc)
        + ((yh * 4) * Xc * Pc + x * Pc + p) * Tc);
    // y-stride = X*P*T = 2048 floats = 512 float4

    float4 c0 = src[0], c1 = src[1];
    #pragma unroll
    for (int yy = 0; yy < 4; yy++) {
        float4 n0 = c0, n1 = c1;
        if (yy < 3) { n0 = src[(yy + 1) * 512]; n1 = src[(yy + 1) * 512 + 1]; }
        int y = yh * 4 + yy;
        float ft0 = c0.x * dtr[0], ft1 = c0.y * dtr[1];
        float ft2 = c0.z * dtr[2], ft3 = c0.w * dtr[3];
        float ft4 = c1.x * dtr[4], ft5 = c1.y * dtr[5];
        float ft6 = c1.z * dtr[6], ft7 = c1.w * dtr[7];
        u64 fb[8];
        fb[0] = pk2(ft0, ft0); fb[1] = pk2(ft1, ft1);
        fb[2] = pk2(ft2, ft2); fb[3] = pk2(ft3, ft3);
        fb[4] = pk2(ft4, ft4); fb[5] = pk2(ft5, ft5);
        fb[6] = pk2(ft6, ft6); fb[7] = pk2(ft7, ft7);
        float dav = sda[y * 16 + x];
        u64 da2 = pk2(dav, dav);
        const u64* klrow = (const u64*)&sklat[y][0];   // 8B-aligned LDS.64
        #pragma unroll
        for (int jj = 0; jj < 4; jj++) {
            u64 wy = mul2_(klrow[jj], da2);            // klat[y]*darea, k-pair
            u64 dd = fb[7];
            #pragma unroll
            for (int t = 6; t >= 0; t--) dd = fma2_(dd, rate2[jj], fb[t]);
            acc[jj] = fma2_(wy, dd, acc[jj]);
        }
        c0 = n0; c1 = n1;
    }

    // (x,p)-dependent factor computed AFTER the loop (no regs held across it)
    float dlp = sdl[p];
    float av[KH];
    #pragma unroll
    for (int jj = 0; jj < 4; jj++) {
        u64 pre = pk2(sklon[x][2 * jj]     * sklev[p][2 * jj]     * dlp,
                      sklon[x][2 * jj + 1] * sklev[p][2 * jj + 1] * dlp);
        u64 r = mul2_(pre, acc[jj]);
        unpk2(r, av[2 * jj], av[2 * jj + 1]);
    }

    // ---- deterministic block reduction: shfl + fixed-order shared sum ----
    #pragma unroll
    for (int j = 0; j < KH; j++) {
        float v = av[j];
        #pragma unroll
        for (int o = 16; o > 0; o >>= 1) v += __shfl_xor_sync(0xFFFFFFFFu, v, o);
        if (lane == 0) sred[warp][j] = v;
    }
    __syncthreads();   // ---- barrier 2 ----

    // ---- finalize: Syx/Sp/St -> winv, scale, store (8 threads) ----
    if (tid < KH) {
        float s = 0.f;
        #pragma unroll
        for (int w = 0; w < 32; w++) s += sred[w][tid];
        float Syx = 0.f;
        #pragma unroll
        for (int w = 0; w < 8; w++) Syx += sint[w][tid];
        float Sp = 0.f;
        #pragma unroll
        for (int pp = 0; pp < Pc; pp++) Sp = fmaf(sklev[pp][tid], sdlmean[pp], Sp);
        float r = srate[tid];
        float St = sdtm[Tc - 1];
        #pragma unroll
        for (int t = Tc - 2; t >= 0; t--) St = fmaf(St, r, sdtm[t]);
        float winv = 1.0f / (Syx * Sp * St + 1e-4f);
        out[b * (Fc * Kc) + f * Kc + kh * KH + tid] = s * winv;
    }
}

extern "C" void kernel_launch(void* const* d_in, const int* in_sizes, int n_in,
                              void* d_out, int out_size)
{
    pkl_fused<<<Bc * Fc * 2, NT>>>(
        (const float*)d_in[0], (const float*)d_in[1],
        (const float*)d_in[2], (const float*)d_in[3],
        (const float*)d_in[4], (const float*)d_in[5],
        (const float*)d_in[6], (const float*)d_in[7],
        (const float*)d_in[8], (const float*)d_in[9],
        (const float*)d_in[10], (float*)d_out);
}

// round 15
// speedup vs baseline: 1.2316x; 1.2316x over previous
#include <cuda_runtime.h>
#include <cstddef>

#define Bc 16
#define Fc 4
#define Kc 16
#define KH 8          // k's per block (k-half)
#define Yc 16
#define Xc 16
#define Pc 16
#define Tc 8
#define NT 1024

typedef unsigned long long u64;

// sm_103a packed f32x2 ops (PTX-only; ptxas never auto-fuses these)
__device__ __forceinline__ u64 pk2(float lo, float hi) {
    u64 r; asm("mov.b64 %0, {%1,%2};" : "=l"(r) : "f"(lo), "f"(hi)); return r;
}
__device__ __forceinline__ void unpk2(u64 v, float& lo, float& hi) {
    asm("mov.b64 {%0,%1}, %2;" : "=f"(lo), "=f"(hi) : "l"(v));
}
__device__ __forceinline__ u64 fma2_(u64 a, u64 b, u64 c) {
    u64 d; asm("fma.rn.f32x2 %0, %1, %2, %3;" : "=l"(d) : "l"(a), "l"(b), "l"(c)); return d;
}
__device__ __forceinline__ u64 mul2_(u64 a, u64 b) {
    u64 d; asm("mul.rn.f32x2 %0, %1, %2;" : "=l"(d) : "l"(a), "l"(b)); return d;
}

// One block = (b, f, k-half). 1024 threads: thread = (yh:2b, x:4b, p:4b),
// each thread contracts 4 y-rows (8 t-values each) for 8 k's.
__global__ void __launch_bounds__(NT, 1) pkl_fused(
    const float* __restrict__ field, const float* __restrict__ darea,
    const float* __restrict__ dlev,  const float* __restrict__ dtime,
    const float* __restrict__ lat_mean, const float* __restrict__ lat_logstd,
    const float* __restrict__ lon_mean, const float* __restrict__ lon_logstd,
    const float* __restrict__ lev_mean, const float* __restrict__ lev_logstd,
    const float* __restrict__ time_logtau, float* __restrict__ out)
{
    int blk = blockIdx.x;
    int kh = blk & 1;
    int f  = (blk >> 1) & 3;
    int b  = blk >> 3;
    int tid  = threadIdx.x;
    int lane = tid & 31;
    int warp = tid >> 5;

    __shared__ __align__(16) float sklat[Yc][KH];
    __shared__ __align__(16) float sklon[Xc][KH];
    __shared__ __align__(16) float sklev[Pc][KH];
    __shared__ float srate[KH], swinv[KH];
    __shared__ float sdamean[Yc * Xc], sda[Yc * Xc];
    __shared__ float sdlmean[Pc], sdl[Pc], sdtm[Tc], sdt[Tc];
    __shared__ float sred[32][KH];

    // ---- 1D parametric kernels for this block's 8 k's (384 gaussians) ----
    if (tid < 3 * 16 * KH) {
        int idx = tid;
        int j   = idx & 7;
        int d   = (idx >> 3) & 15;
        int dim = idx >> 7;
        int fk  = f * Kc + kh * KH + j;
        float coord = -1.0f + 2.0f * (float)d / 15.0f;
        float m, ls;
        if (dim == 0)      { m = lat_mean[fk]; ls = lat_logstd[fk]; }
        else if (dim == 1) { m = lon_mean[fk]; ls = lon_logstd[fk]; }
        else               { m = lev_mean[fk]; ls = lev_logstd[fk]; }
        float z = (coord - m) * expf(-ls);
        float g = expf(-0.5f * z * z);
        if (dim == 0)      sklat[d][j] = g;
        else if (dim == 1) sklon[d][j] = g;
        else               sklev[d][j] = g;
    }
    if (tid >= 512 && tid < 512 + KH) {
        int j = tid - 512;
        int fk = f * Kc + kh * KH + j;
        float tau = expf(time_logtau[fk]) + 1e-4f;
        srate[j] = expf(-1.0f / tau);       // ktime[t] = rate^t
    }
    // ---- batch means + this sample's quadrature weights ----
    if (tid >= 768 && tid < 1024) {
        int i = tid - 768;
        float s = 0.f;
        #pragma unroll
        for (int bb = 0; bb < Bc; bb++) s += darea[bb * 256 + i];
        sdamean[i] = s * (1.f / 16.f);
        sda[i] = darea[b * 256 + i];
    }
    if (tid >= 704 && tid < 704 + Pc) {
        int i = tid - 704;
        float s = 0.f;
        #pragma unroll
        for (int bb = 0; bb < Bc; bb++) s += dlev[bb * Pc + i];
        sdlmean[i] = s * (1.f / 16.f);
        sdl[i] = dlev[b * Pc + i];
    }
    if (tid >= 736 && tid < 736 + Tc) {
        int i = tid - 736;
        float s = 0.f;
        #pragma unroll
        for (int bb = 0; bb < Bc; bb++) s += dtime[bb * Tc + i];
        sdtm[i] = s * (1.f / 16.f);
        sdt[i] = dtime[b * Tc + i];
    }
    __syncthreads();

    // ---- separable normalization integral -> 1/(I + eps) ----
    {
        float c[KH];
        #pragma unroll
        for (int j = 0; j < KH; j++) c[j] = 0.f;
        if (tid < 256) {
            int yi = tid >> 4, xi = tid & 15;
            float dm = sdamean[tid];
            #pragma unroll
            for (int j = 0; j < KH; j++) c[j] = dm * sklat[yi][j] * sklon[xi][j];
        }
        if (warp < 8) {
            #pragma unroll
            for (int j = 0; j < KH; j++) {
                float v = c[j];
                #pragma unroll
                for (int o = 16; o > 0; o >>= 1) v += __shfl_xor_sync(0xFFFFFFFFu, v, o);
                if (lane == 0) sred[warp][j] = v;
            }
        }
        __syncthreads();
        if (tid < KH) {
            float Syx = 0.f;
            #pragma unroll
            for (int w = 0; w < 8; w++) Syx += sred[w][tid];
            float Sp = 0.f;
            #pragma unroll
            for (int p = 0; p < Pc; p++) Sp = fmaf(sklev[p][tid], sdlmean[p], Sp);
            float r = srate[tid];
            float St = sdtm[Tc - 1];
            #pragma unroll
            for (int t = Tc - 2; t >= 0; t--) St = fmaf(St, r, sdtm[t]);
            swinv[tid] = 1.0f / (Syx * Sp * St + 1e-4f);
        }
        __syncthreads();   // sred reused below; swinv must be visible
    }

    // ---- main contraction: thread = (yh, x, p); 4 rows of 8 t-values ----
    int p  = tid & 15;
    int x  = (tid >> 4) & 15;
    int yh = tid >> 8;                     // 0..3
    u64 rate2[4];
    #pragma unroll
    for (int jj = 0; jj < 4; jj++) rate2[jj] = pk2(srate[2 * jj], srate[2 * jj + 1]);
    float dtr[Tc];
    #pragma unroll
    for (int t = 0; t < Tc; t++) dtr[t] = sdt[t];
    u64 acc[4];
    #pragma unroll
    for (int jj = 0; jj < 4; jj++) acc[jj] = pk2(0.f, 0.f);

    const float4* src = (const float4*)(field
        + (size_t)(b * Fc + f) * (Yc * Xc * Pc * Tc)
        + ((yh * 4) * Xc * Pc + x * Pc + p) * Tc);
    // y-stride = X*P*T = 2048 floats = 512 float4

    float4 c0 = src[0], c1 = src[1];
    #pragma unroll
    for (int yy = 0; yy < 4; yy++) {
        float4 n0 = c0, n1 = c1;
        if (yy < 3) { n0 = src[(yy + 1) * 512]; n1 = src[(yy + 1) * 512 + 1]; }
        int y = yh * 4 + yy;
        float ft0 = c0.x * dtr[0], ft1 = c0.y * dtr[1];
        float ft2 = c0.z * dtr[2], ft3 = c0.w * dtr[3];
        float ft4 = c1.x * dtr[4], ft5 = c1.y * dtr[5];
        float ft6 = c1.z * dtr[6], ft7 = c1.w * dtr[7];
        u64 fb[8];
        fb[0] = pk2(ft0, ft0); fb[1] = pk2(ft1, ft1);
        fb[2] = pk2(ft2, ft2); fb[3] = pk2(ft3, ft3);
        fb[4] = pk2(ft4, ft4); fb[5] = pk2(ft5, ft5);
        fb[6] = pk2(ft6, ft6); fb[7] = pk2(ft7, ft7);
        float dav = sda[y * 16 + x];
        u64 da2 = pk2(dav, dav);
        const u64* klrow = (const u64*)&sklat[y][0];   // 8B-aligned LDS.64
        #pragma unroll
        for (int jj = 0; jj < 4; jj++) {
            u64 wy = mul2_(klrow[jj], da2);            // klat[y]*darea, k-pair
            u64 dd = fb[7];
            #pragma unroll
            for (int t = 6; t >= 0; t--) dd = fma2_(dd, rate2[jj], fb[t]);
            acc[jj] = fma2_(wy, dd, acc[jj]);
        }
        c0 = n0; c1 = n1;
    }

    // apply the (x,p)-dependent factor once, after the y/t loop
    float dlp = sdl[p];
    float av[KH];
    #pragma unroll
    for (int jj = 0; jj < 4; jj++) {
        u64 pre = pk2(sklon[x][2 * jj]     * sklev[p][2 * jj]     * dlp,
                      sklon[x][2 * jj + 1] * sklev[p][2 * jj + 1] * dlp);
        u64 r = mul2_(pre, acc[jj]);
        unpk2(r, av[2 * jj], av[2 * jj + 1]);
    }

    // ---- deterministic block reduction: shfl + fixed-order shared sum ----
    #pragma unroll
    for (int j = 0; j < KH; j++) {
        float v = av[j];
        #pragma unroll
        for (int o = 16; o > 0; o >>= 1) v += __shfl_xor_sync(0xFFFFFFFFu, v, o);
        if (lane == 0) sred[warp][j] = v;
    }
    __syncthreads();
    if (tid < KH) {
        float s = 0.f;
        #pragma unroll
        for (int w = 0; w < 32; w++) s += sred[w][tid];
        out[b * (Fc * Kc) + f * Kc + kh * KH + tid] = s * swinv[tid];
    }
}

extern "C" void kernel_launch(void* const* d_in, const int* in_sizes, int n_in,
                              void* d_out, int out_size)
{
    pkl_fused<<<Bc * Fc * 2, NT>>>(
        (const float*)d_in[0], (const float*)d_in[1],
        (const float*)d_in[2], (const float*)d_in[3],
        (const float*)d_in[4], (const float*)d_in[5],
        (const float*)d_in[6], (const float*)d_in[7],
        (const float*)d_in[8], (const float*)d_in[9],
        (const float*)d_in[10], (float*)d_out);
}